// round 12
// baseline (speedup 1.0000x reference)
#include <cuda_runtime.h>

// Problem dims (compile-time, from reference)
#define BDIM 2
#define CDIM 3
#define DDIM 128
#define HDIM 192
#define WDIM 192

// ---------------------------------------------------------------------------
// X pass (R9 measured-best ~59.5us): warp-transpose solve along W.
// ---------------------------------------------------------------------------
constexpr int XWARPS = 8;
constexpr int XTPB   = XWARPS * 32;

__global__ __launch_bounds__(XTPB) void solve_x_kernel(
    const float* __restrict__ in, float* __restrict__ out,
    const float* __restrict__ a, const float* __restrict__ b,
    const float* __restrict__ c)
{
    __shared__ float tile[XWARPS][32][33];
    __shared__ float s_inva[WDIM], s_b[WDIM], s_c[WDIM];

    const int t    = threadIdx.x;
    const int wid  = t >> 5;
    const int lane = t & 31;

    for (int i = t; i < WDIM; i += XTPB) {
        s_inva[i] = 1.0f / a[i];
        if (i < WDIM - 1) { s_b[i] = b[i]; s_c[i] = c[i]; }
    }
    __syncthreads();

    float (*tl)[33] = tile[wid];
    const int line0 = (blockIdx.x * XWARPS + wid) * 32;
    const int r0 = lane >> 3;
    const int cm = (lane & 7) * 4;

    float carry = 0.0f;
    float yreg[32];

    // forward sweep
    for (int k = 0; k < 6; k++) {
        const int c0 = k * 32;
        #pragma unroll
        for (int rr = 0; rr < 32; rr += 4) {
            const int r = rr + r0;
            float4 v = *(const float4*)(in + (size_t)(line0 + r) * WDIM + c0 + cm);
            tl[r][cm]     = v.x; tl[r][cm + 1] = v.y;
            tl[r][cm + 2] = v.z; tl[r][cm + 3] = v.w;
        }
        __syncwarp();
        #pragma unroll
        for (int j = 0; j < 32; j++) {
            const float x = tl[lane][j];
            const int i = c0 + j;
            carry = (i == 0) ? x : fmaf(-s_c[i - 1], carry, x);
            yreg[j] = carry;
        }
        if (k < 5) {
            #pragma unroll
            for (int j = 0; j < 32; j++) tl[lane][j] = yreg[j];
            __syncwarp();
            #pragma unroll
            for (int rr = 0; rr < 32; rr += 4) {
                const int r = rr + r0;
                float4 v = make_float4(tl[r][cm], tl[r][cm + 1],
                                       tl[r][cm + 2], tl[r][cm + 3]);
                *(float4*)(out + (size_t)(line0 + r) * WDIM + c0 + cm) = v;
            }
        }
        __syncwarp();
    }

    // backward sweep: chunk 5 from registers
    {
        const int c0 = 5 * 32;
        #pragma unroll
        for (int j = 31; j >= 0; j--) {
            const int i = c0 + j;
            const float x = yreg[j];
            carry = (i == WDIM - 1) ? x * s_inva[i]
                                    : fmaf(-s_b[i], carry, x) * s_inva[i];
            yreg[j] = carry;
        }
        #pragma unroll
        for (int j = 0; j < 32; j++) tl[lane][j] = yreg[j];
        __syncwarp();
        #pragma unroll
        for (int rr = 0; rr < 32; rr += 4) {
            const int r = rr + r0;
            float4 v = make_float4(tl[r][cm], tl[r][cm + 1],
                                   tl[r][cm + 2], tl[r][cm + 3]);
            *(float4*)(out + (size_t)(line0 + r) * WDIM + c0 + cm) = v;
        }
        __syncwarp();
    }
    for (int k = 4; k >= 0; k--) {
        const int c0 = k * 32;
        #pragma unroll
        for (int rr = 0; rr < 32; rr += 4) {
            const int r = rr + r0;
            float4 v = *(const float4*)(out + (size_t)(line0 + r) * WDIM + c0 + cm);
            tl[r][cm]     = v.x; tl[r][cm + 1] = v.y;
            tl[r][cm + 2] = v.z; tl[r][cm + 3] = v.w;
        }
        __syncwarp();
        #pragma unroll
        for (int j = 31; j >= 0; j--) {
            const int i = c0 + j;
            carry = fmaf(-s_b[i], carry, tl[lane][j]) * s_inva[i];
            yreg[j] = carry;
        }
        #pragma unroll
        for (int j = 0; j < 32; j++) tl[lane][j] = yreg[j];
        __syncwarp();
        #pragma unroll
        for (int rr = 0; rr < 32; rr += 4) {
            const int r = rr + r0;
            float4 v = make_float4(tl[r][cm], tl[r][cm + 1],
                                   tl[r][cm + 2], tl[r][cm + 3]);
            *(float4*)(out + (size_t)(line0 + r) * WDIM + c0 + cm) = v;
        }
        __syncwarp();
    }
}

// ---------------------------------------------------------------------------
// Split strided solve: each line is solved by TWO threads (halves A/B) via
// partitioned Thomas. Forward: both halves run with carry-in 0; B fixes up
// with y_mid * H_i (H = homogeneous solution, precomputed per block).
// Backward mirrored with G. y stays fully in registers (N/2 per thread);
// global traffic = read + write only, zero spill.
//   block = 128 threads = 64 lines x 2 halves; t%64 = line, t/64 = half.
// ---------------------------------------------------------------------------
constexpr int STPB  = 128;
constexpr int LPB   = 64;     // lines per block

template <int N, int STRIDE>
__global__ __launch_bounds__(STPB) void solve_split_kernel(
    float* __restrict__ data,
    const float* __restrict__ a, const float* __restrict__ b,
    const float* __restrict__ c, int wchunks, int outer_stride)
{
    constexpr int HN = N / 2;
    __shared__ float s_inva[N], s_binva[N], s_c[N];
    __shared__ float s_H[HN], s_G[HN];
    __shared__ float xch_y[LPB], xch_z[LPB];

    const int t = threadIdx.x;
    for (int i = t; i < N; i += STPB) {
        const float iv = 1.0f / a[i];
        s_inva[i]  = iv;
        s_binva[i] = (i < N - 1) ? b[i] * iv : 0.0f;
        s_c[i]     = (i < N - 1) ? c[i] : 0.0f;
    }
    __syncthreads();

    // Homogeneous solutions (serial, by threads 0/1, overlapped with the
    // forward global loads of all other threads; the post-forward
    // __syncthreads publishes them before fixup).
    if (t == 0) {
        float h = -s_c[HN - 1];
        s_H[0] = h;
        for (int i = 1; i < HN; i++) { h = -s_c[HN + i - 1] * h; s_H[i] = h; }
    }
    if (t == 1) {
        float g = -s_binva[HN - 1];
        s_G[HN - 1] = g;
        for (int i = HN - 2; i >= 0; i--) { g = -s_binva[i] * g; s_G[i] = g; }
    }

    const int li   = t & (LPB - 1);     // line within block
    const int half = t >> 6;            // 0 = A (low), 1 = B (high)

    const int bid   = blockIdx.x;
    const int outer = bid / wchunks;
    const int wc    = bid - outer * wchunks;
    float* p = data + (size_t)outer * outer_stride + wc * LPB + li;

    float y[HN];
    float carry;

    // ---- forward (both halves, carry-in 0 for B) ----
    if (half == 0) {
        carry = p[0];
        y[0] = carry;
        #pragma unroll
        for (int i = 1; i < HN; i++) {
            carry = fmaf(-s_c[i - 1], carry, p[(size_t)i * STRIDE]);
            y[i] = carry;
        }
        xch_y[li] = carry;              // y_{HN-1}
    } else {
        carry = p[(size_t)HN * STRIDE];
        y[0] = carry;
        #pragma unroll
        for (int i = 1; i < HN; i++) {
            const int gi = HN + i;
            carry = fmaf(-s_c[gi - 1], carry, p[(size_t)gi * STRIDE]);
            y[i] = carry;
        }
    }
    __syncthreads();

    // ---- B: fixup + backward (stores high half, exports z_{HN}) ----
    if (half == 1) {
        const float ym = xch_y[li];
        #pragma unroll
        for (int i = 0; i < HN; i++) y[i] = fmaf(ym, s_H[i], y[i]);

        carry = 0.0f;
        #pragma unroll
        for (int i = HN - 1; i >= 0; i--) {
            const int gi = HN + i;
            carry = fmaf(-s_binva[gi], carry, y[i] * s_inva[gi]);
            p[(size_t)gi * STRIDE] = carry;
        }
        xch_z[li] = carry;              // z_{HN}
    } else {
        // ---- A: backward with assumed z_{HN}=0 (z' held in regs) ----
        carry = 0.0f;
        #pragma unroll
        for (int i = HN - 1; i >= 0; i--) {
            carry = fmaf(-s_binva[i], carry, y[i] * s_inva[i]);
            y[i] = carry;
        }
    }
    __syncthreads();

    // ---- A: fixup + store low half ----
    if (half == 0) {
        const float zm = xch_z[li];
        #pragma unroll
        for (int i = 0; i < HN; i++)
            p[(size_t)i * STRIDE] = fmaf(zm, s_G[i], y[i]);
    }
}

// ---------------------------------------------------------------------------
// Launch
// ---------------------------------------------------------------------------
extern "C" void kernel_launch(void* const* d_in, const int* in_sizes, int n_in,
                              void* d_out, int out_size)
{
    const float* field = (const float*)d_in[0];
    const float* ax = (const float*)d_in[1];
    const float* bx = (const float*)d_in[2];
    const float* cx = (const float*)d_in[3];
    const float* ay = (const float*)d_in[4];
    const float* by = (const float*)d_in[5];
    const float* cy = (const float*)d_in[6];
    const float* az = (const float*)d_in[7];
    const float* bz = (const float*)d_in[8];
    const float* cz = (const float*)d_in[9];
    float* out = (float*)d_out;

    (void)in_sizes; (void)n_in; (void)out_size;

    // X: 147456 lines / 256 = 576 blocks
    const int lines_x = BDIM * CDIM * DDIM * HDIM;
    solve_x_kernel<<<lines_x / (XWARPS * 32), XTPB>>>(field, out, ax, bx, cx);

    // Y: outer = (b,c,d), wchunks = W/64 = 3, stride W, outer_stride H*W
    const int blocks_y = BDIM * CDIM * DDIM * (WDIM / LPB);
    solve_split_kernel<HDIM, WDIM><<<blocks_y, STPB>>>(
        out, ay, by, cy, WDIM / LPB, HDIM * WDIM);

    // Z: outer = (b,c,h), wchunks = W/64 = 3, stride H*W; outer index maps
    // (b,c,h) -> bc*(D*H*W) + h*W. outer_stride trick: outer = bc*H + h,
    // base = outer/H * (D*H*W) + (outer%H) * W  -- handled by passing
    // outer_stride = WDIM and folding D into the stride? No: use a wrapper
    // mapping below via wchunks = H*(W/64) per (b,c).
    const int blocks_z = BDIM * CDIM * HDIM * (WDIM / LPB);
    solve_split_kernel<DDIM, HDIM * WDIM><<<blocks_z, STPB>>>(
        out, az, bz, cz, HDIM * (WDIM / LPB), DDIM * HDIM * WDIM);
}

// round 14
// speedup vs baseline: 1.0789x; 1.0789x over previous
#include <cuda_runtime.h>

// Problem dims (compile-time, from reference)
#define BDIM 2
#define CDIM 3
#define DDIM 128
#define HDIM 192
#define WDIM 192

// ---------------------------------------------------------------------------
// X pass: warp-transpose solve along W, float2 smem ops (PADW=34 floats =
// 17 float2 -> conflict-free 64-bit LDS/STS for both row-walk and staging).
// 6 chunks of 32 cols; y chunks 0-4 round-trip via out (L2), chunk 5 in regs.
// ---------------------------------------------------------------------------
constexpr int XWARPS = 8;
constexpr int XTPB   = XWARPS * 32;
constexpr int PAD2   = 17;              // float2 per row (34 floats)

__global__ __launch_bounds__(XTPB) void solve_x_kernel(
    const float* __restrict__ in, float* __restrict__ out,
    const float* __restrict__ a, const float* __restrict__ b,
    const float* __restrict__ c)
{
    __shared__ float2 tile2[XWARPS][32][PAD2];
    __shared__ float s_inva[WDIM], s_b[WDIM], s_c[WDIM];

    const int t    = threadIdx.x;
    const int wid  = t >> 5;
    const int lane = t & 31;

    for (int i = t; i < WDIM; i += XTPB) {
        s_inva[i] = 1.0f / a[i];
        if (i < WDIM - 1) { s_b[i] = b[i]; s_c[i] = c[i]; }
    }
    __syncthreads();

    float2 (*tl)[PAD2] = tile2[wid];
    const int line0 = (blockIdx.x * XWARPS + wid) * 32;
    const int r0  = lane >> 3;           // 0..3
    const int cm  = (lane & 7) * 4;      // 0,4,...,28
    const int cg  = cm >> 1;             // float2 granule: 0,2,...,14

    float carry = 0.0f;
    float yreg[32];

    // ---------------- forward sweep ----------------
    for (int k = 0; k < 6; k++) {
        const int c0 = k * 32;
        #pragma unroll
        for (int rr = 0; rr < 32; rr += 4) {
            const int r = rr + r0;
            float4 v = *(const float4*)(in + (size_t)(line0 + r) * WDIM + c0 + cm);
            tl[r][cg]     = make_float2(v.x, v.y);
            tl[r][cg + 1] = make_float2(v.z, v.w);
        }
        __syncwarp();
        #pragma unroll
        for (int jj = 0; jj < 16; jj++) {
            const float2 v = tl[lane][jj];
            const int i = c0 + 2 * jj;
            const float c1 = (i == 0) ? v.x : fmaf(-s_c[i - 1], carry, v.x);
            const float c2 = fmaf(-s_c[i], c1, v.y);
            yreg[2 * jj] = c1; yreg[2 * jj + 1] = c2;
            carry = c2;
        }
        if (k < 5) {
            #pragma unroll
            for (int jj = 0; jj < 16; jj++)
                tl[lane][jj] = make_float2(yreg[2 * jj], yreg[2 * jj + 1]);
            __syncwarp();
            #pragma unroll
            for (int rr = 0; rr < 32; rr += 4) {
                const int r = rr + r0;
                const float2 p0 = tl[r][cg], p1 = tl[r][cg + 1];
                *(float4*)(out + (size_t)(line0 + r) * WDIM + c0 + cm) =
                    make_float4(p0.x, p0.y, p1.x, p1.y);
            }
        }
        __syncwarp();
    }

    // ---------------- backward sweep ----------------
    // chunk 5 from registers
    {
        const int c0 = 5 * 32;
        #pragma unroll
        for (int jj = 15; jj >= 0; jj--) {
            const int i1 = c0 + 2 * jj + 1;
            const int i0 = c0 + 2 * jj;
            const float yh = yreg[2 * jj + 1];
            carry = (i1 == WDIM - 1) ? yh * s_inva[i1]
                                     : fmaf(-s_b[i1], carry, yh) * s_inva[i1];
            yreg[2 * jj + 1] = carry;
            carry = fmaf(-s_b[i0], carry, yreg[2 * jj]) * s_inva[i0];
            yreg[2 * jj] = carry;
        }
        #pragma unroll
        for (int jj = 0; jj < 16; jj++)
            tl[lane][jj] = make_float2(yreg[2 * jj], yreg[2 * jj + 1]);
        __syncwarp();
        #pragma unroll
        for (int rr = 0; rr < 32; rr += 4) {
            const int r = rr + r0;
            const float2 p0 = tl[r][cg], p1 = tl[r][cg + 1];
            *(float4*)(out + (size_t)(line0 + r) * WDIM + 5 * 32 + cm) =
                make_float4(p0.x, p0.y, p1.x, p1.y);
        }
        __syncwarp();
    }
    for (int k = 4; k >= 0; k--) {
        const int c0 = k * 32;
        #pragma unroll
        for (int rr = 0; rr < 32; rr += 4) {
            const int r = rr + r0;
            float4 v = *(const float4*)(out + (size_t)(line0 + r) * WDIM + c0 + cm);
            tl[r][cg]     = make_float2(v.x, v.y);
            tl[r][cg + 1] = make_float2(v.z, v.w);
        }
        __syncwarp();
        #pragma unroll
        for (int jj = 15; jj >= 0; jj--) {
            const float2 v = tl[lane][jj];
            const int i1 = c0 + 2 * jj + 1;
            const int i0 = c0 + 2 * jj;
            carry = fmaf(-s_b[i1], carry, v.y) * s_inva[i1];
            const float zhi = carry;
            carry = fmaf(-s_b[i0], carry, v.x) * s_inva[i0];
            tl[lane][jj] = make_float2(carry, zhi);
        }
        __syncwarp();
        #pragma unroll
        for (int rr = 0; rr < 32; rr += 4) {
            const int r = rr + r0;
            const float2 p0 = tl[r][cg], p1 = tl[r][cg + 1];
            *(float4*)(out + (size_t)(line0 + r) * WDIM + c0 + cm) =
                make_float4(p0.x, p0.y, p1.x, p1.y);
        }
        __syncwarp();
    }
}

// ---------------------------------------------------------------------------
// Strided passes (R8 solve, 64-thread blocks for occupancy): scalar
// thread-per-line, y register-held for last HOLD steps; first N-HOLD steps
// round-trip through global (L2-hot).
// ---------------------------------------------------------------------------
template <int N, int HOLD, int STRIDE>
__device__ __forceinline__ void solve_line_reg(
    float* __restrict__ p,
    const float* __restrict__ s_inva,
    const float* __restrict__ s_binva,
    const float* __restrict__ s_c)
{
    constexpr int SPILL = N - HOLD;
    float yreg[HOLD];
    float carry;

    carry = p[0];
    if (SPILL > 0) p[0] = carry; else yreg[0] = carry;
    #pragma unroll
    for (int i = 1; i < N; i++) {
        carry = fmaf(-s_c[i - 1], carry, p[(size_t)i * STRIDE]);
        if (i < SPILL) p[(size_t)i * STRIDE] = carry;
        else           yreg[i - SPILL] = carry;
    }

    carry = 0.0f;
    #pragma unroll
    for (int i = N - 1; i >= SPILL; i--) {
        carry = fmaf(-s_binva[i], carry, yreg[i - SPILL] * s_inva[i]);
        p[(size_t)i * STRIDE] = carry;
    }
    #pragma unroll
    for (int i = SPILL - 1; i >= 0; i--) {
        carry = fmaf(-s_binva[i], carry, p[(size_t)i * STRIDE] * s_inva[i]);
        p[(size_t)i * STRIDE] = carry;
    }
}

constexpr int STPB = 64;

template <int N>
__device__ __forceinline__ void load_coeffs_s(
    const float* __restrict__ a, const float* __restrict__ b,
    const float* __restrict__ c,
    float* __restrict__ s_inva, float* __restrict__ s_binva,
    float* __restrict__ s_c)
{
    for (int i = threadIdx.x; i < N; i += STPB) {
        const float iv = 1.0f / a[i];
        s_inva[i]  = iv;
        s_binva[i] = (i < N - 1) ? b[i] * iv : 0.0f;
        s_c[i]     = (i < N - 1) ? c[i] : 0.0f;
    }
}

__global__ __launch_bounds__(STPB, 1) void solve_y_kernel(
    float* __restrict__ data,
    const float* __restrict__ a, const float* __restrict__ b,
    const float* __restrict__ c)
{
    __shared__ float s_inva[HDIM], s_binva[HDIM], s_c[HDIM];
    load_coeffs_s<HDIM>(a, b, c, s_inva, s_binva, s_c);
    __syncthreads();

    const int L   = blockIdx.x * STPB + threadIdx.x;  // line over (b,c,d) x w
    const int bcd = L / WDIM;
    const int w   = L - bcd * WDIM;
    float* p = data + (size_t)bcd * (HDIM * WDIM) + w;
    solve_line_reg<HDIM, 128, WDIM>(p, s_inva, s_binva, s_c);
}

__global__ __launch_bounds__(STPB, 1) void solve_z_kernel(
    float* __restrict__ data,
    const float* __restrict__ a, const float* __restrict__ b,
    const float* __restrict__ c)
{
    __shared__ float s_inva[DDIM], s_binva[DDIM], s_c[DDIM];
    load_coeffs_s<DDIM>(a, b, c, s_inva, s_binva, s_c);
    __syncthreads();

    const int L  = blockIdx.x * STPB + threadIdx.x;   // line over (b,c) x (h,w)
    const int bc = L / (HDIM * WDIM);
    const int hw = L - bc * (HDIM * WDIM);
    float* p = data + (size_t)bc * (DDIM * HDIM * WDIM) + hw;
    solve_line_reg<DDIM, DDIM, HDIM * WDIM>(p, s_inva, s_binva, s_c);
}

// ---------------------------------------------------------------------------
// Launch
// ---------------------------------------------------------------------------
extern "C" void kernel_launch(void* const* d_in, const int* in_sizes, int n_in,
                              void* d_out, int out_size)
{
    const float* field = (const float*)d_in[0];
    const float* ax = (const float*)d_in[1];
    const float* bx = (const float*)d_in[2];
    const float* cx = (const float*)d_in[3];
    const float* ay = (const float*)d_in[4];
    const float* by = (const float*)d_in[5];
    const float* cy = (const float*)d_in[6];
    const float* az = (const float*)d_in[7];
    const float* bz = (const float*)d_in[8];
    const float* cz = (const float*)d_in[9];
    float* out = (float*)d_out;

    (void)in_sizes; (void)n_in; (void)out_size;

    // X: 147456 lines / 256 = 576 blocks
    const int lines_x = BDIM * CDIM * DDIM * HDIM;
    solve_x_kernel<<<lines_x / (XWARPS * 32), XTPB>>>(field, out, ax, bx, cx);

    // Y: lines = b*c*d*w = 147456 / 64 = 2304 blocks
    const int lines_y = BDIM * CDIM * DDIM * WDIM;
    solve_y_kernel<<<lines_y / STPB, STPB>>>(out, ay, by, cy);

    // Z: lines = b*c*h*w = 221184 / 64 = 3456 blocks
    const int lines_z = BDIM * CDIM * HDIM * WDIM;
    solve_z_kernel<<<lines_z / STPB, STPB>>>(out, az, bz, cz);
}

// round 16
// speedup vs baseline: 1.0950x; 1.0149x over previous
#include <cuda_runtime.h>

// Problem dims (compile-time, from reference)
#define BDIM 2
#define CDIM 3
#define DDIM 128
#define HDIM 192
#define WDIM 192

// ---------------------------------------------------------------------------
// X pass (R14 measured-best): warp-transpose solve along W, float2 smem ops
// (PAD2=17 float2/row -> conflict-free 64-bit LDS/STS). 6 chunks of 32 cols;
// y chunks 0-4 round-trip via out (L2), chunk 5 in regs.
// ---------------------------------------------------------------------------
constexpr int XWARPS = 8;
constexpr int XTPB   = XWARPS * 32;
constexpr int PAD2   = 17;              // float2 per row (34 floats)

__global__ __launch_bounds__(XTPB) void solve_x_kernel(
    const float* __restrict__ in, float* __restrict__ out,
    const float* __restrict__ a, const float* __restrict__ b,
    const float* __restrict__ c)
{
    __shared__ float2 tile2[XWARPS][32][PAD2];
    __shared__ float s_inva[WDIM], s_b[WDIM], s_c[WDIM];

    const int t    = threadIdx.x;
    const int wid  = t >> 5;
    const int lane = t & 31;

    for (int i = t; i < WDIM; i += XTPB) {
        s_inva[i] = 1.0f / a[i];
        if (i < WDIM - 1) { s_b[i] = b[i]; s_c[i] = c[i]; }
    }
    __syncthreads();

    float2 (*tl)[PAD2] = tile2[wid];
    const int line0 = (blockIdx.x * XWARPS + wid) * 32;
    const int r0  = lane >> 3;           // 0..3
    const int cm  = (lane & 7) * 4;      // 0,4,...,28
    const int cg  = cm >> 1;             // float2 granule: 0,2,...,14

    float carry = 0.0f;
    float yreg[32];

    // ---------------- forward sweep ----------------
    for (int k = 0; k < 6; k++) {
        const int c0 = k * 32;
        #pragma unroll
        for (int rr = 0; rr < 32; rr += 4) {
            const int r = rr + r0;
            float4 v = *(const float4*)(in + (size_t)(line0 + r) * WDIM + c0 + cm);
            tl[r][cg]     = make_float2(v.x, v.y);
            tl[r][cg + 1] = make_float2(v.z, v.w);
        }
        __syncwarp();
        #pragma unroll
        for (int jj = 0; jj < 16; jj++) {
            const float2 v = tl[lane][jj];
            const int i = c0 + 2 * jj;
            const float c1 = (i == 0) ? v.x : fmaf(-s_c[i - 1], carry, v.x);
            const float c2 = fmaf(-s_c[i], c1, v.y);
            yreg[2 * jj] = c1; yreg[2 * jj + 1] = c2;
            carry = c2;
        }
        if (k < 5) {
            #pragma unroll
            for (int jj = 0; jj < 16; jj++)
                tl[lane][jj] = make_float2(yreg[2 * jj], yreg[2 * jj + 1]);
            __syncwarp();
            #pragma unroll
            for (int rr = 0; rr < 32; rr += 4) {
                const int r = rr + r0;
                const float2 p0 = tl[r][cg], p1 = tl[r][cg + 1];
                *(float4*)(out + (size_t)(line0 + r) * WDIM + c0 + cm) =
                    make_float4(p0.x, p0.y, p1.x, p1.y);
            }
        }
        __syncwarp();
    }

    // ---------------- backward sweep ----------------
    // chunk 5 from registers
    {
        const int c0 = 5 * 32;
        #pragma unroll
        for (int jj = 15; jj >= 0; jj--) {
            const int i1 = c0 + 2 * jj + 1;
            const int i0 = c0 + 2 * jj;
            const float yh = yreg[2 * jj + 1];
            carry = (i1 == WDIM - 1) ? yh * s_inva[i1]
                                     : fmaf(-s_b[i1], carry, yh) * s_inva[i1];
            yreg[2 * jj + 1] = carry;
            carry = fmaf(-s_b[i0], carry, yreg[2 * jj]) * s_inva[i0];
            yreg[2 * jj] = carry;
        }
        #pragma unroll
        for (int jj = 0; jj < 16; jj++)
            tl[lane][jj] = make_float2(yreg[2 * jj], yreg[2 * jj + 1]);
        __syncwarp();
        #pragma unroll
        for (int rr = 0; rr < 32; rr += 4) {
            const int r = rr + r0;
            const float2 p0 = tl[r][cg], p1 = tl[r][cg + 1];
            *(float4*)(out + (size_t)(line0 + r) * WDIM + 5 * 32 + cm) =
                make_float4(p0.x, p0.y, p1.x, p1.y);
        }
        __syncwarp();
    }
    for (int k = 4; k >= 0; k--) {
        const int c0 = k * 32;
        #pragma unroll
        for (int rr = 0; rr < 32; rr += 4) {
            const int r = rr + r0;
            float4 v = *(const float4*)(out + (size_t)(line0 + r) * WDIM + c0 + cm);
            tl[r][cg]     = make_float2(v.x, v.y);
            tl[r][cg + 1] = make_float2(v.z, v.w);
        }
        __syncwarp();
        #pragma unroll
        for (int jj = 15; jj >= 0; jj--) {
            const float2 v = tl[lane][jj];
            const int i1 = c0 + 2 * jj + 1;
            const int i0 = c0 + 2 * jj;
            carry = fmaf(-s_b[i1], carry, v.y) * s_inva[i1];
            const float zhi = carry;
            carry = fmaf(-s_b[i0], carry, v.x) * s_inva[i0];
            tl[lane][jj] = make_float2(carry, zhi);
        }
        __syncwarp();
        #pragma unroll
        for (int rr = 0; rr < 32; rr += 4) {
            const int r = rr + r0;
            const float2 p0 = tl[r][cg], p1 = tl[r][cg + 1];
            *(float4*)(out + (size_t)(line0 + r) * WDIM + c0 + cm) =
                make_float4(p0.x, p0.y, p1.x, p1.y);
        }
        __syncwarp();
    }
}

// ---------------------------------------------------------------------------
// Strided passes: scalar thread-per-line (coalesced across w), y FULLY
// register-held (HOLD == N for both Y and Z -> zero spill traffic).
// 64-thread blocks.
// ---------------------------------------------------------------------------
template <int N, int HOLD, int STRIDE>
__device__ __forceinline__ void solve_line_reg(
    float* __restrict__ p,
    const float* __restrict__ s_inva,
    const float* __restrict__ s_binva,
    const float* __restrict__ s_c)
{
    constexpr int SPILL = N - HOLD;
    float yreg[HOLD];
    float carry;

    carry = p[0];
    if (SPILL > 0) p[0] = carry; else yreg[0] = carry;
    #pragma unroll
    for (int i = 1; i < N; i++) {
        carry = fmaf(-s_c[i - 1], carry, p[(size_t)i * STRIDE]);
        if (i < SPILL) p[(size_t)i * STRIDE] = carry;
        else           yreg[i - SPILL] = carry;
    }

    carry = 0.0f;
    #pragma unroll
    for (int i = N - 1; i >= SPILL; i--) {
        carry = fmaf(-s_binva[i], carry, yreg[i - SPILL] * s_inva[i]);
        p[(size_t)i * STRIDE] = carry;
    }
    #pragma unroll
    for (int i = SPILL - 1; i >= 0; i--) {
        carry = fmaf(-s_binva[i], carry, p[(size_t)i * STRIDE] * s_inva[i]);
        p[(size_t)i * STRIDE] = carry;
    }
}

constexpr int STPB = 64;

template <int N>
__device__ __forceinline__ void load_coeffs_s(
    const float* __restrict__ a, const float* __restrict__ b,
    const float* __restrict__ c,
    float* __restrict__ s_inva, float* __restrict__ s_binva,
    float* __restrict__ s_c)
{
    for (int i = threadIdx.x; i < N; i += STPB) {
        const float iv = 1.0f / a[i];
        s_inva[i]  = iv;
        s_binva[i] = (i < N - 1) ? b[i] * iv : 0.0f;
        s_c[i]     = (i < N - 1) ? c[i] : 0.0f;
    }
}

__global__ __launch_bounds__(STPB, 1) void solve_y_kernel(
    float* __restrict__ data,
    const float* __restrict__ a, const float* __restrict__ b,
    const float* __restrict__ c)
{
    __shared__ float s_inva[HDIM], s_binva[HDIM], s_c[HDIM];
    load_coeffs_s<HDIM>(a, b, c, s_inva, s_binva, s_c);
    __syncthreads();

    const int L   = blockIdx.x * STPB + threadIdx.x;  // line over (b,c,d) x w
    const int bcd = L / WDIM;
    const int w   = L - bcd * WDIM;
    float* p = data + (size_t)bcd * (HDIM * WDIM) + w;
    solve_line_reg<HDIM, HDIM, WDIM>(p, s_inva, s_binva, s_c);   // zero spill
}

__global__ __launch_bounds__(STPB, 1) void solve_z_kernel(
    float* __restrict__ data,
    const float* __restrict__ a, const float* __restrict__ b,
    const float* __restrict__ c)
{
    __shared__ float s_inva[DDIM], s_binva[DDIM], s_c[DDIM];
    load_coeffs_s<DDIM>(a, b, c, s_inva, s_binva, s_c);
    __syncthreads();

    const int L  = blockIdx.x * STPB + threadIdx.x;   // line over (b,c) x (h,w)
    const int bc = L / (HDIM * WDIM);
    const int hw = L - bc * (HDIM * WDIM);
    float* p = data + (size_t)bc * (DDIM * HDIM * WDIM) + hw;
    solve_line_reg<DDIM, DDIM, HDIM * WDIM>(p, s_inva, s_binva, s_c);
}

// ---------------------------------------------------------------------------
// Launch
// ---------------------------------------------------------------------------
extern "C" void kernel_launch(void* const* d_in, const int* in_sizes, int n_in,
                              void* d_out, int out_size)
{
    const float* field = (const float*)d_in[0];
    const float* ax = (const float*)d_in[1];
    const float* bx = (const float*)d_in[2];
    const float* cx = (const float*)d_in[3];
    const float* ay = (const float*)d_in[4];
    const float* by = (const float*)d_in[5];
    const float* cy = (const float*)d_in[6];
    const float* az = (const float*)d_in[7];
    const float* bz = (const float*)d_in[8];
    const float* cz = (const float*)d_in[9];
    float* out = (float*)d_out;

    (void)in_sizes; (void)n_in; (void)out_size;

    // X: 147456 lines / 256 = 576 blocks
    const int lines_x = BDIM * CDIM * DDIM * HDIM;
    solve_x_kernel<<<lines_x / (XWARPS * 32), XTPB>>>(field, out, ax, bx, cx);

    // Y: lines = b*c*d*w = 147456 / 64 = 2304 blocks
    const int lines_y = BDIM * CDIM * DDIM * WDIM;
    solve_y_kernel<<<lines_y / STPB, STPB>>>(out, ay, by, cy);

    // Z: lines = b*c*h*w = 221184 / 64 = 3456 blocks
    const int lines_z = BDIM * CDIM * HDIM * WDIM;
    solve_z_kernel<<<lines_z / STPB, STPB>>>(out, az, bz, cz);
}

// round 17
// speedup vs baseline: 1.1213x; 1.0240x over previous
#include <cuda_runtime.h>

// Problem dims (compile-time, from reference)
#define BDIM 2
#define CDIM 3
#define DDIM 128
#define HDIM 192
#define WDIM 192

// ---------------------------------------------------------------------------
// X pass: warp-transpose solve along W, float2 smem ops (PAD2=17).
// Chunks 3-5 (96 y-values) register-held; only chunks 0-2 round-trip via out.
// Fully unrolled chunk loop -> compile-time yreg indexing.
// ---------------------------------------------------------------------------
constexpr int XWARPS = 8;
constexpr int XTPB   = XWARPS * 32;
constexpr int PAD2   = 17;              // float2 per row (34 floats)

__global__ __launch_bounds__(XTPB) void solve_x_kernel(
    const float* __restrict__ in, float* __restrict__ out,
    const float* __restrict__ a, const float* __restrict__ b,
    const float* __restrict__ c)
{
    __shared__ float2 tile2[XWARPS][32][PAD2];
    __shared__ float s_inva[WDIM], s_b[WDIM], s_c[WDIM];

    const int t    = threadIdx.x;
    const int wid  = t >> 5;
    const int lane = t & 31;

    for (int i = t; i < WDIM; i += XTPB) {
        s_inva[i] = 1.0f / a[i];
        if (i < WDIM - 1) { s_b[i] = b[i]; s_c[i] = c[i]; }
    }
    __syncthreads();

    float2 (*tl)[PAD2] = tile2[wid];
    const int line0 = (blockIdx.x * XWARPS + wid) * 32;
    const int r0  = lane >> 3;           // 0..3
    const int cm  = (lane & 7) * 4;      // 0,4,...,28
    const int cg  = cm >> 1;             // float2 granule: 0,2,...,14

    float carry = 0.0f;
    float yreg[96];                      // chunks 3,4,5

    // ---------------- forward sweep ----------------
    #pragma unroll
    for (int k = 0; k < 6; k++) {
        const int c0 = k * 32;
        #pragma unroll
        for (int rr = 0; rr < 32; rr += 4) {
            const int r = rr + r0;
            float4 v = *(const float4*)(in + (size_t)(line0 + r) * WDIM + c0 + cm);
            tl[r][cg]     = make_float2(v.x, v.y);
            tl[r][cg + 1] = make_float2(v.z, v.w);
        }
        __syncwarp();
        if (k < 3) {
            // solve in-tile, stage y to out
            #pragma unroll
            for (int jj = 0; jj < 16; jj++) {
                const float2 v = tl[lane][jj];
                const int i = c0 + 2 * jj;
                const float c1 = (i == 0) ? v.x : fmaf(-s_c[i - 1], carry, v.x);
                const float c2 = fmaf(-s_c[i], c1, v.y);
                tl[lane][jj] = make_float2(c1, c2);
                carry = c2;
            }
            __syncwarp();
            #pragma unroll
            for (int rr = 0; rr < 32; rr += 4) {
                const int r = rr + r0;
                const float2 p0 = tl[r][cg], p1 = tl[r][cg + 1];
                *(float4*)(out + (size_t)(line0 + r) * WDIM + c0 + cm) =
                    make_float4(p0.x, p0.y, p1.x, p1.y);
            }
        } else {
            // solve into registers
            const int o = (k - 3) * 32;
            #pragma unroll
            for (int jj = 0; jj < 16; jj++) {
                const float2 v = tl[lane][jj];
                const int i = c0 + 2 * jj;
                const float c1 = fmaf(-s_c[i - 1], carry, v.x);
                const float c2 = fmaf(-s_c[i], c1, v.y);
                yreg[o + 2 * jj] = c1; yreg[o + 2 * jj + 1] = c2;
                carry = c2;
            }
        }
        __syncwarp();
    }

    // ---------------- backward sweep ----------------
    // chunks 5,4,3 from registers
    #pragma unroll
    for (int kk = 0; kk < 3; kk++) {
        const int k  = 5 - kk;
        const int c0 = k * 32;
        const int o  = (k - 3) * 32;
        #pragma unroll
        for (int jj = 15; jj >= 0; jj--) {
            const int i1 = c0 + 2 * jj + 1;
            const int i0 = c0 + 2 * jj;
            const float yh = yreg[o + 2 * jj + 1];
            carry = (i1 == WDIM - 1) ? yh * s_inva[i1]
                                     : fmaf(-s_b[i1], carry, yh) * s_inva[i1];
            yreg[o + 2 * jj + 1] = carry;
            carry = fmaf(-s_b[i0], carry, yreg[o + 2 * jj]) * s_inva[i0];
            yreg[o + 2 * jj] = carry;
        }
        #pragma unroll
        for (int jj = 0; jj < 16; jj++)
            tl[lane][jj] = make_float2(yreg[o + 2 * jj], yreg[o + 2 * jj + 1]);
        __syncwarp();
        #pragma unroll
        for (int rr = 0; rr < 32; rr += 4) {
            const int r = rr + r0;
            const float2 p0 = tl[r][cg], p1 = tl[r][cg + 1];
            *(float4*)(out + (size_t)(line0 + r) * WDIM + c0 + cm) =
                make_float4(p0.x, p0.y, p1.x, p1.y);
        }
        __syncwarp();
    }
    // chunks 2,1,0: reload y from out (L2-hot)
    #pragma unroll
    for (int k = 2; k >= 0; k--) {
        const int c0 = k * 32;
        #pragma unroll
        for (int rr = 0; rr < 32; rr += 4) {
            const int r = rr + r0;
            float4 v = *(const float4*)(out + (size_t)(line0 + r) * WDIM + c0 + cm);
            tl[r][cg]     = make_float2(v.x, v.y);
            tl[r][cg + 1] = make_float2(v.z, v.w);
        }
        __syncwarp();
        #pragma unroll
        for (int jj = 15; jj >= 0; jj--) {
            const float2 v = tl[lane][jj];
            const int i1 = c0 + 2 * jj + 1;
            const int i0 = c0 + 2 * jj;
            carry = fmaf(-s_b[i1], carry, v.y) * s_inva[i1];
            const float zhi = carry;
            carry = fmaf(-s_b[i0], carry, v.x) * s_inva[i0];
            tl[lane][jj] = make_float2(carry, zhi);
        }
        __syncwarp();
        #pragma unroll
        for (int rr = 0; rr < 32; rr += 4) {
            const int r = rr + r0;
            const float2 p0 = tl[r][cg], p1 = tl[r][cg + 1];
            *(float4*)(out + (size_t)(line0 + r) * WDIM + c0 + cm) =
                make_float4(p0.x, p0.y, p1.x, p1.y);
        }
        __syncwarp();
    }
}

// ---------------------------------------------------------------------------
// Strided passes: scalar thread-per-line (coalesced across w). Y: HOLD=160
// (under the 255-reg ceiling; 32-step spill via global/L2). Z: fully held.
// 64-thread blocks.
// ---------------------------------------------------------------------------
template <int N, int HOLD, int STRIDE>
__device__ __forceinline__ void solve_line_reg(
    float* __restrict__ p,
    const float* __restrict__ s_inva,
    const float* __restrict__ s_binva,
    const float* __restrict__ s_c)
{
    constexpr int SPILL = N - HOLD;
    float yreg[HOLD];
    float carry;

    carry = p[0];
    if (SPILL > 0) p[0] = carry; else yreg[0] = carry;
    #pragma unroll
    for (int i = 1; i < N; i++) {
        carry = fmaf(-s_c[i - 1], carry, p[(size_t)i * STRIDE]);
        if (i < SPILL) p[(size_t)i * STRIDE] = carry;
        else           yreg[i - SPILL] = carry;
    }

    carry = 0.0f;
    #pragma unroll
    for (int i = N - 1; i >= SPILL; i--) {
        carry = fmaf(-s_binva[i], carry, yreg[i - SPILL] * s_inva[i]);
        p[(size_t)i * STRIDE] = carry;
    }
    #pragma unroll
    for (int i = SPILL - 1; i >= 0; i--) {
        carry = fmaf(-s_binva[i], carry, p[(size_t)i * STRIDE] * s_inva[i]);
        p[(size_t)i * STRIDE] = carry;
    }
}

constexpr int STPB = 64;

template <int N>
__device__ __forceinline__ void load_coeffs_s(
    const float* __restrict__ a, const float* __restrict__ b,
    const float* __restrict__ c,
    float* __restrict__ s_inva, float* __restrict__ s_binva,
    float* __restrict__ s_c)
{
    for (int i = threadIdx.x; i < N; i += STPB) {
        const float iv = 1.0f / a[i];
        s_inva[i]  = iv;
        s_binva[i] = (i < N - 1) ? b[i] * iv : 0.0f;
        s_c[i]     = (i < N - 1) ? c[i] : 0.0f;
    }
}

__global__ __launch_bounds__(STPB, 1) void solve_y_kernel(
    float* __restrict__ data,
    const float* __restrict__ a, const float* __restrict__ b,
    const float* __restrict__ c)
{
    __shared__ float s_inva[HDIM], s_binva[HDIM], s_c[HDIM];
    load_coeffs_s<HDIM>(a, b, c, s_inva, s_binva, s_c);
    __syncthreads();

    const int L   = blockIdx.x * STPB + threadIdx.x;  // line over (b,c,d) x w
    const int bcd = L / WDIM;
    const int w   = L - bcd * WDIM;
    float* p = data + (size_t)bcd * (HDIM * WDIM) + w;
    solve_line_reg<HDIM, 160, WDIM>(p, s_inva, s_binva, s_c);
}

__global__ __launch_bounds__(STPB, 1) void solve_z_kernel(
    float* __restrict__ data,
    const float* __restrict__ a, const float* __restrict__ b,
    const float* __restrict__ c)
{
    __shared__ float s_inva[DDIM], s_binva[DDIM], s_c[DDIM];
    load_coeffs_s<DDIM>(a, b, c, s_inva, s_binva, s_c);
    __syncthreads();

    const int L  = blockIdx.x * STPB + threadIdx.x;   // line over (b,c) x (h,w)
    const int bc = L / (HDIM * WDIM);
    const int hw = L - bc * (HDIM * WDIM);
    float* p = data + (size_t)bc * (DDIM * HDIM * WDIM) + hw;
    solve_line_reg<DDIM, DDIM, HDIM * WDIM>(p, s_inva, s_binva, s_c);
}

// ---------------------------------------------------------------------------
// Launch
// ---------------------------------------------------------------------------
extern "C" void kernel_launch(void* const* d_in, const int* in_sizes, int n_in,
                              void* d_out, int out_size)
{
    const float* field = (const float*)d_in[0];
    const float* ax = (const float*)d_in[1];
    const float* bx = (const float*)d_in[2];
    const float* cx = (const float*)d_in[3];
    const float* ay = (const float*)d_in[4];
    const float* by = (const float*)d_in[5];
    const float* cy = (const float*)d_in[6];
    const float* az = (const float*)d_in[7];
    const float* bz = (const float*)d_in[8];
    const float* cz = (const float*)d_in[9];
    float* out = (float*)d_out;

    (void)in_sizes; (void)n_in; (void)out_size;

    // X: 147456 lines / 256 = 576 blocks
    const int lines_x = BDIM * CDIM * DDIM * HDIM;
    solve_x_kernel<<<lines_x / (XWARPS * 32), XTPB>>>(field, out, ax, bx, cx);

    // Y: lines = b*c*d*w = 147456 / 64 = 2304 blocks
    const int lines_y = BDIM * CDIM * DDIM * WDIM;
    solve_y_kernel<<<lines_y / STPB, STPB>>>(out, ay, by, cy);

    // Z: lines = b*c*h*w = 221184 / 64 = 3456 blocks
    const int lines_z = BDIM * CDIM * HDIM * WDIM;
    solve_z_kernel<<<lines_z / STPB, STPB>>>(out, az, bz, cz);
}